// round 17
// baseline (speedup 1.0000x reference)
#include <cuda_runtime.h>

// B=16, Wn=64, K=256, E=128, O=64

typedef unsigned long long ull;

__device__ __forceinline__ ull f2_add(ull a, ull b) {
    ull r; asm("add.rn.f32x2 %0,%1,%2;" : "=l"(r) : "l"(a), "l"(b)); return r;
}
__device__ __forceinline__ ull f2_fma(ull a, ull b, ull c) {
    ull r; asm("fma.rn.f32x2 %0,%1,%2,%3;" : "=l"(r) : "l"(a), "l"(b), "l"(c)); return r;
}
__device__ __forceinline__ float f2_hadd(ull a) {
    float lo, hi; asm("mov.b64 {%0,%1},%2;" : "=f"(lo), "=f"(hi) : "l"(a)); return lo + hi;
}
__device__ __forceinline__ ull f2_dup(float v) {
    ull r; asm("mov.b64 %0,{%1,%1};" : "=l"(r) : "f"(v)); return r;
}
__device__ __forceinline__ void f2_unpack(ull a, float& lo, float& hi) {
    asm("mov.b64 {%0,%1},%2;" : "=f"(lo), "=f"(hi) : "l"(a));
}

// Scratch
__device__ float g_L[16 * 256 * 128];
__device__ float g_R[16 * 256 * 128];
__device__ float g_sLp[2 * 16 * 256];   // per-e-half partial row dots (no atomics)
__device__ float g_sRp[2 * 16 * 256];
__device__ float g_h[16 * 256 * 64];

// ---------------------------------------------------------------------------
// k1: C[4096,256] = A[4096,64] x W[256,64]^T ; 4m x 4n register tiles,
// fused sL/sR partial row-dots (scale 0.6) via shfl + plain store.
// grid 256, 256 thr.
// ---------------------------------------------------------------------------
__global__ void __launch_bounds__(256, 3)
k1_lr(const float* __restrict__ x, const float* __restrict__ lin_w,
      const float* __restrict__ lin_b, const float* __restrict__ a) {
    __shared__ float As[64 * 68];
    __shared__ float Ws[64 * 68];

    int bx = blockIdx.x;
    int mt = bx >> 2, nt = bx & 3;
    int b = mt >> 2, k0 = (mt & 3) * 64;
    int half = nt >> 1, e0 = (nt & 1) * 64;
    int tid = threadIdx.x;

#pragma unroll
    for (int t = 0; t < 4; t++) {
        int idx = t * 256 + tid;
        int w = idx >> 4, m4 = idx & 15;
        float4 v = *reinterpret_cast<const float4*>(x + b * 16384 + w * 256 + k0 + m4 * 4);
        *reinterpret_cast<float4*>(&As[w * 68 + m4 * 4]) = v;
    }
#pragma unroll
    for (int t = 0; t < 4; t++) {
        int idx = t * 256 + tid;
        int n = idx >> 4, w4 = idx & 15;
        float4 v = *reinterpret_cast<const float4*>(lin_w + (e0 + n) * 128 + half * 64 + w4 * 4);
        Ws[(w4 * 4 + 0) * 68 + n] = v.x;
        Ws[(w4 * 4 + 1) * 68 + n] = v.y;
        Ws[(w4 * 4 + 2) * 68 + n] = v.z;
        Ws[(w4 * 4 + 3) * 68 + n] = v.w;
    }
    __syncthreads();

    int mg = tid >> 4, ng = tid & 15;
    ull acc[4][2];
#pragma unroll
    for (int n = 0; n < 4; n++) { acc[n][0] = 0ULL; acc[n][1] = 0ULL; }

#pragma unroll 8
    for (int w = 0; w < 64; w++) {
        const ull* ap = reinterpret_cast<const ull*>(&As[w * 68 + mg * 4]);
        ull a0 = ap[0], a1 = ap[1];
        float4 wn = *reinterpret_cast<const float4*>(&Ws[w * 68 + ng * 4]);
        ull w0 = f2_dup(wn.x), w1 = f2_dup(wn.y), w2 = f2_dup(wn.z), w3 = f2_dup(wn.w);
        acc[0][0] = f2_fma(a0, w0, acc[0][0]); acc[0][1] = f2_fma(a1, w0, acc[0][1]);
        acc[1][0] = f2_fma(a0, w1, acc[1][0]); acc[1][1] = f2_fma(a1, w1, acc[1][1]);
        acc[2][0] = f2_fma(a0, w2, acc[2][0]); acc[2][1] = f2_fma(a1, w2, acc[2][1]);
        acc[3][0] = f2_fma(a0, w3, acc[3][0]); acc[3][1] = f2_fma(a1, w3, acc[3][1]);
    }

    float4 lb4 = make_float4(0.f, 0.f, 0.f, 0.f);
    if (half == 0) lb4 = *reinterpret_cast<const float4*>(lin_b + e0 + ng * 4);
    float4 a6 = *reinterpret_cast<const float4*>(a + e0 + ng * 4);
    a6.x *= 0.6f; a6.y *= 0.6f; a6.z *= 0.6f; a6.w *= 0.6f;

    float* outbase = (half ? g_R : g_L) + (b * 256 + k0 + mg * 4) * 128 + e0 + ng * 4;
    float part[4];
#pragma unroll
    for (int p = 0; p < 2; p++) {
        float lo[4], hi[4];
#pragma unroll
        for (int n = 0; n < 4; n++) f2_unpack(acc[n][p], lo[n], hi[n]);
        float l0 = lo[0] + lb4.x, l1 = lo[1] + lb4.y, l2 = lo[2] + lb4.z, l3 = lo[3] + lb4.w;
        float h0 = hi[0] + lb4.x, h1 = hi[1] + lb4.y, h2 = hi[2] + lb4.z, h3 = hi[3] + lb4.w;
        *reinterpret_cast<float4*>(outbase + (2 * p) * 128) = make_float4(l0, l1, l2, l3);
        *reinterpret_cast<float4*>(outbase + (2 * p + 1) * 128) = make_float4(h0, h1, h2, h3);
        part[2 * p]     = l0 * a6.x + l1 * a6.y + l2 * a6.z + l3 * a6.w;
        part[2 * p + 1] = h0 * a6.x + h1 * a6.y + h2 * a6.z + h3 * a6.w;
    }
#pragma unroll
    for (int o = 8; o > 0; o >>= 1) {
#pragma unroll
        for (int r = 0; r < 4; r++)
            part[r] += __shfl_down_sync(0xffffffffu, part[r], o, 16);
    }
    if (ng == 0) {
        float* sp = (half ? g_sRp : g_sLp) + (e0 ? 4096 : 0) + b * 256 + k0 + mg * 4;
#pragma unroll
        for (int r = 0; r < 4; r++) sp[r] = part[r];
    }
}

// ---------------------------------------------------------------------------
// k2: e = sL+sR + sum(0.4a)|L+R| + bias; softmax; h = sigmoid(p @ v).
// grid = 128 (16b x 8 itiles of 32), 256 thr.
// e-phase: 4 eh x 4 ig x 16 jg; 8i x 4j register tiles;
// R staged via cp.async (8B granules) 2-buffer ring, ONE sync per jt stage.
// smem 218,368 B.
// ---------------------------------------------------------------------------
__global__ void __launch_bounds__(256, 1)
k2_attn(const float* __restrict__ x, const float* __restrict__ bias_kk,
        const float* __restrict__ a) {
    extern __shared__ float S[];
    const int LS = 0;        // 32 x 132
    const int RS0 = 4224;    // 64 x 130  (ring buf 0; later xs j-half 0)
    const int RS1 = 12544;   // 64 x 130  (ring buf 1)
    const int E0 = 20864;    // 32 x 260  -> probabilities after softmax
    const int E1 = 29184;    // 32 x 260  -> xs j-half 1 after softmax
    const int E2 = 37504;    // 32 x 260
    const int E3 = 45824;    // 32 x 260
    const int CS = 54144;    // 128 (0.4*a)
    const int SRS = 54272;   // 256
    const int SLS = 54528;   // 32
    const int INVS = 54560;  // 32   (total 54592 floats = 218,368 B)
    const ull ABSM = 0x7FFFFFFF7FFFFFFFULL;

    int tid = threadIdx.x;
    int b = blockIdx.x >> 3;
    int i0 = (blockIdx.x & 7) << 5;
    unsigned smem_u32 = (unsigned)__cvta_generic_to_shared(S);

    const float* Rgb = g_R + (b * 256) * 128;

    // issue cp.async (8B) for R stage 0 immediately; overlaps L staging.
    // 64 rows x 64 ull-chunks = 4096 chunks, 16 per thread.
    {
#pragma unroll
        for (int t = 0; t < 16; t++) {
            int idx = t * 256 + tid;
            int row = idx >> 6, j2 = idx & 63;
            unsigned sm = smem_u32 + (unsigned)(RS0 + row * 130 + j2 * 2) * 4u;
            asm volatile("cp.async.ca.shared.global [%0], [%1], 8;"
                         :: "r"(sm), "l"(Rgb + row * 128 + j2 * 2) : "memory");
        }
        asm volatile("cp.async.commit_group;" ::: "memory");
    }

    const float* Lg = g_L + (b * 256 + i0) * 128;
#pragma unroll
    for (int t = 0; t < 4; t++) {
        int idx = t * 256 + tid;
        int row = idx >> 5, c4 = idx & 31;
        float4 v = *reinterpret_cast<const float4*>(Lg + row * 128 + c4 * 4);
        *reinterpret_cast<float4*>(&S[LS + row * 132 + c4 * 4]) = v;
    }
    if (tid < 128) S[CS + tid] = 0.4f * a[tid];
    S[SRS + tid] = g_sRp[b * 256 + tid] + g_sRp[4096 + b * 256 + tid];
    if (tid < 32)
        S[SLS + tid] = g_sLp[b * 256 + i0 + tid] + g_sLp[4096 + b * 256 + i0 + tid];

    int eh = tid >> 6;          // e-quarter 0..3
    int r = tid & 63;
    int ig = r >> 4;            // 0..3 -> rows ig + 4u
    int jg = r & 15;            // 0..15 -> cols jt*64 + jg + 16v
    const ull* Lp[8];
#pragma unroll
    for (int u = 0; u < 8; u++)
        Lp[u] = reinterpret_cast<const ull*>(&S[LS + (ig + 4 * u) * 132]) + eh * 16;
    const ull* Cp = reinterpret_cast<const ull*>(&S[CS]) + eh * 16;
    float* Eq = &S[E0 + eh * 8320];

    for (int jt = 0; jt < 4; jt++) {
        asm volatile("cp.async.wait_group 0;" ::: "memory");
        __syncthreads();   // stage jt landed; prior reads of other buffer done

        if (jt < 3) {       // issue stage jt+1 into the other buffer
            int nbase = ((jt + 1) & 1) ? RS1 : RS0;
            const float* Rgn = Rgb + (jt + 1) * 64 * 128;
#pragma unroll
            for (int t = 0; t < 16; t++) {
                int idx = t * 256 + tid;
                int row = idx >> 6, j2 = idx & 63;
                unsigned sm = smem_u32 + (unsigned)(nbase + row * 130 + j2 * 2) * 4u;
                asm volatile("cp.async.ca.shared.global [%0], [%1], 8;"
                             :: "r"(sm), "l"(Rgn + row * 128 + j2 * 2) : "memory");
            }
            asm volatile("cp.async.commit_group;" ::: "memory");
        }

        int Rb = (jt & 1) ? RS1 : RS0;
        const ull* Rp0 = reinterpret_cast<const ull*>(&S[Rb + (jg) * 130]) + eh * 16;
        const ull* Rp1 = reinterpret_cast<const ull*>(&S[Rb + (jg + 16) * 130]) + eh * 16;
        const ull* Rp2 = reinterpret_cast<const ull*>(&S[Rb + (jg + 32) * 130]) + eh * 16;
        const ull* Rp3 = reinterpret_cast<const ull*>(&S[Rb + (jg + 48) * 130]) + eh * 16;

        ull acc[8][4];
#pragma unroll
        for (int u = 0; u < 8; u++)
#pragma unroll
            for (int v = 0; v < 4; v++) acc[u][v] = 0ULL;

#pragma unroll 2
        for (int ep = 0; ep < 16; ep++) {
            ull c = Cp[ep];
            ull r0 = Rp0[ep], r1 = Rp1[ep], r2 = Rp2[ep], r3 = Rp3[ep];
#pragma unroll
            for (int u = 0; u < 8; u++) {
                ull l = Lp[u][ep];
                acc[u][0] = f2_fma(f2_add(l, r0) & ABSM, c, acc[u][0]);
                acc[u][1] = f2_fma(f2_add(l, r1) & ABSM, c, acc[u][1]);
                acc[u][2] = f2_fma(f2_add(l, r2) & ABSM, c, acc[u][2]);
                acc[u][3] = f2_fma(f2_add(l, r3) & ABSM, c, acc[u][3]);
            }
        }
#pragma unroll
        for (int u = 0; u < 8; u++) {
            int i = ig + 4 * u;
#pragma unroll
            for (int v = 0; v < 4; v++) {
                int j = jt * 64 + jg + 16 * v;
                Eq[i * 260 + j] = f2_hadd(acc[u][v]);
            }
        }
    }
    __syncthreads();

    // Issue x j-half-0 LDGs now; latency hidden behind softmax.
    float4 xh0[8];
#pragma unroll
    for (int t = 0; t < 8; t++) {
        int idx = t * 256 + tid;
        int row = idx >> 5, c4 = idx & 31;
        xh0[t] = *reinterpret_cast<const float4*>(x + b * 16384 + row * 256 + c4 * 4);
    }

    // softmax over j: 8 warps x 4 rows; fold 4 e-quarters + linear terms
    int wid = tid >> 5, lane = tid & 31;
#pragma unroll
    for (int s = 0; s < 4; s++) {
        int rr = wid * 4 + s;
        float sl = S[SLS + rr];
        const float* bp = bias_kk + (i0 + rr) * 256;
        float v[8];
        float m = -1e30f;
#pragma unroll
        for (int u = 0; u < 8; u++) {
            int c = u * 32 + lane;
            int o = rr * 260 + c;
            v[u] = S[E0 + o] + S[E1 + o] + S[E2 + o] + S[E3 + o]
                 + sl + S[SRS + c] + bp[c];
            m = fmaxf(m, v[u]);
        }
#pragma unroll
        for (int o = 16; o > 0; o >>= 1) m = fmaxf(m, __shfl_xor_sync(0xffffffffu, m, o));
        float sum = 0.f;
#pragma unroll
        for (int u = 0; u < 8; u++) {
            float p = __expf(v[u] - m);
            S[E0 + rr * 260 + u * 32 + lane] = p;
            sum += p;
        }
#pragma unroll
        for (int o = 16; o > 0; o >>= 1) sum += __shfl_xor_sync(0xffffffffu, sum, o);
        if (lane == 0) S[INVS + rr] = 1.f / sum;
    }

    // store x j-half-0 into RS0 (free; all warps passed post-e-phase barrier)
#pragma unroll
    for (int t = 0; t < 8; t++) {
        int idx = t * 256 + tid;
        int row = idx >> 5, c4 = idx & 31;
        float* d = &S[RS0 + row * 130 + c4 * 4];
        *reinterpret_cast<float2*>(d) = make_float2(xh0[t].x, xh0[t].y);
        *reinterpret_cast<float2*>(d + 2) = make_float2(xh0[t].z, xh0[t].w);
    }
    __syncthreads();

    // stage x j-half-1 into E1 (free after softmax; probs live in E0)
#pragma unroll
    for (int t = 0; t < 8; t++) {
        int idx = t * 256 + tid;
        int row = idx >> 5, c4 = idx & 31;
        float4 v = *reinterpret_cast<const float4*>(x + b * 16384 + row * 256 + 128 + c4 * 4);
        float* d = &S[E1 + row * 130 + c4 * 4];
        *reinterpret_cast<float2*>(d) = make_float2(v.x, v.y);
        *reinterpret_cast<float2*>(d + 2) = make_float2(v.z, v.w);
    }
    __syncthreads();

    // h: thread = (w in 64, ih = i-quarter of 8); f[8] over full j
    int w = tid & 63;
    int ih = tid >> 6;
    ull f[8];
#pragma unroll
    for (int ii = 0; ii < 8; ii++) f[ii] = 0ULL;
    const float* pb = &S[E0 + (ih * 8) * 260];
    const ull* xq0 = reinterpret_cast<const ull*>(&S[RS0 + w * 130]);
    const ull* xq1 = reinterpret_cast<const ull*>(&S[E1 + w * 130]);
    for (int j4 = 0; j4 < 32; j4++) {
        ull x0 = xq0[j4 * 2], x1 = xq0[j4 * 2 + 1];
#pragma unroll
        for (int ii = 0; ii < 8; ii++) {
            ulonglong2 pq = *reinterpret_cast<const ulonglong2*>(pb + ii * 260 + j4 * 4);
            f[ii] = f2_fma(x0, pq.x, f[ii]);
            f[ii] = f2_fma(x1, pq.y, f[ii]);
        }
    }
    for (int j4 = 0; j4 < 32; j4++) {
        ull x0 = xq1[j4 * 2], x1 = xq1[j4 * 2 + 1];
#pragma unroll
        for (int ii = 0; ii < 8; ii++) {
            ulonglong2 pq = *reinterpret_cast<const ulonglong2*>(pb + ii * 260 + 128 + j4 * 4);
            f[ii] = f2_fma(x0, pq.x, f[ii]);
            f[ii] = f2_fma(x1, pq.y, f[ii]);
        }
    }
#pragma unroll
    for (int ii = 0; ii < 8; ii++) {
        int i = ih * 8 + ii;
        float val = f2_hadd(f[ii]) * S[INVS + i];
        g_h[(b * 256 + i0 + i) * 64 + w] = 1.f / (1.f + __expf(-val));
    }
}

// ---------------------------------------------------------------------------
// k3: out[b,w,o] = sum_k h[b,k,w] fc_w[o,k] + fc_b[o]
// grid = 128 (16b x 8 wtiles of 8), 256 thr, single staging + 1 sync
// ---------------------------------------------------------------------------
__global__ void __launch_bounds__(256, 2)
k3_fc(const float* __restrict__ fc_w, const float* __restrict__ fc_b,
      float* __restrict__ out) {
    extern __shared__ float T[];
    const int FW = 0;       // 64 x 258
    const int HS = 16512;   // 8 x 258

    int bx = blockIdx.x;
    int b = bx >> 3, wq = bx & 7;
    int w0 = wq * 8;
    int tid = threadIdx.x;
    int w8 = tid & 7, og = tid >> 3;

    // h staging first (scalar, worst latency) so its LDGs lead the window
#pragma unroll
    for (int t = 0; t < 8; t++) {
        int idx = t * 256 + tid;
        int kk = idx >> 3, ww = idx & 7;
        T[HS + ww * 258 + kk] = g_h[(b * 256 + kk) * 64 + w0 + ww];
    }
#pragma unroll
    for (int t = 0; t < 16; t++) {
        int idx = t * 256 + tid;
        int row = idx >> 6, c4 = idx & 63;
        float4 v = *reinterpret_cast<const float4*>(fc_w + row * 256 + c4 * 4);
        float* d = &T[FW + row * 258 + c4 * 4];
        *reinterpret_cast<float2*>(d) = make_float2(v.x, v.y);
        *reinterpret_cast<float2*>(d + 2) = make_float2(v.z, v.w);
    }
    __syncthreads();

    const ull* hp = reinterpret_cast<const ull*>(&T[HS + w8 * 258]);
    const ull* f0 = reinterpret_cast<const ull*>(&T[FW + og * 258]);
    const ull* f1 = reinterpret_cast<const ull*>(&T[FW + (og + 32) * 258]);
    ull acc0 = 0ULL, acc1 = 0ULL;
#pragma unroll 16
    for (int kp = 0; kp < 128; kp++) {
        ull h2 = hp[kp];
        acc0 = f2_fma(h2, f0[kp], acc0);
        acc1 = f2_fma(h2, f1[kp], acc1);
    }
    out[(b * 64 + w0 + w8) * 64 + og] = f2_hadd(acc0) + fc_b[og];
    out[(b * 64 + w0 + w8) * 64 + og + 32] = f2_hadd(acc1) + fc_b[og + 32];
}

// ---------------------------------------------------------------------------
extern "C" void kernel_launch(void* const* d_in, const int* in_sizes, int n_in,
                              void* d_out, int out_size) {
    const float* x       = (const float*)d_in[0];
    const float* lin_w   = (const float*)d_in[1];
    const float* lin_b   = (const float*)d_in[2];
    const float* a       = (const float*)d_in[3];
    const float* bias_kk = (const float*)d_in[4];
    const float* fc_w    = (const float*)d_in[5];
    const float* fc_b    = (const float*)d_in[6];
    float* out = (float*)d_out;

    cudaFuncSetAttribute(k2_attn, cudaFuncAttributeMaxDynamicSharedMemorySize, 218368);
    cudaFuncSetAttribute(k3_fc, cudaFuncAttributeMaxDynamicSharedMemorySize, 74304);

    k1_lr<<<256, 256>>>(x, lin_w, lin_b, a);
    k2_attn<<<128, 256, 218368>>>(x, bias_kk, a);
    k3_fc<<<128, 256, 74304>>>(fc_w, fc_b, out);
}